// round 15
// baseline (speedup 1.0000x reference)
#include <cuda_runtime.h>
#include <cuda_fp16.h>
#include <math.h>
#include <stdint.h>

#define B_ 16
#define C_ 512
#define HW_ 4096
#define HEADS_ 8
#define HK_ 64
#define CTX_SPLIT 8

// ------------------------- scratch (device globals) -------------------------
__device__ __half g_xt[(size_t)B_ * HW_ * C_];   // x transposed fp16 [b][l][c]
__device__ __half g_kh[(size_t)B_ * C_ * HW_];   // raw k logits fp16
__device__ __half g_vh[(size_t)B_ * C_ * HW_];
__device__ __half g_qt[(size_t)B_ * HW_ * C_];   // softmaxed q transposed [b][l][512]
__device__ float  g_ctxf[CTX_SPLIT * B_ * HEADS_ * HK_ * HK_];
__device__ __half g_mb[(size_t)B_ * C_ * C_];    // folded Wr@ctxT [b][o][512]
__device__ __half g_wc[1536 * 512];              // q | k | v weights fp16
__device__ float g_bcat[1536];
__device__ float g_kmx[B_ * C_];
__device__ float g_kinv[B_ * C_];

// ------------------------- PTX helpers -------------------------
__device__ __forceinline__ uint32_t smem_u32(const void* p) {
    return (uint32_t)__cvta_generic_to_shared(p);
}
__device__ __forceinline__ void cp16(uint32_t dst, const void* src) {
    asm volatile("cp.async.cg.shared.global [%0], [%1], 16;\n" :: "r"(dst), "l"(src));
}
__device__ __forceinline__ void cp_commit() {
    asm volatile("cp.async.commit_group;\n" ::: "memory");
}
template <int N>
__device__ __forceinline__ void cp_wait() {
    asm volatile("cp.async.wait_group %0;\n" :: "n"(N) : "memory");
}
__device__ __forceinline__ uint32_t sw128(uint32_t off) {
    return off ^ ((off >> 3) & 0x70);
}
__device__ __forceinline__ void ldsm4(uint32_t& r0, uint32_t& r1, uint32_t& r2,
                                      uint32_t& r3, uint32_t addr) {
    asm volatile("ldmatrix.sync.aligned.m8n8.x4.shared.b16 {%0,%1,%2,%3}, [%4];"
                 : "=r"(r0), "=r"(r1), "=r"(r2), "=r"(r3) : "r"(addr));
}
__device__ __forceinline__ void mma16816(float* c, uint32_t a0, uint32_t a1,
                                         uint32_t a2, uint32_t a3,
                                         uint32_t b0, uint32_t b1) {
    asm volatile(
        "mma.sync.aligned.m16n8k16.row.col.f32.f16.f16.f32 "
        "{%0,%1,%2,%3}, {%4,%5,%6,%7}, {%8,%9}, {%0,%1,%2,%3};"
        : "+f"(c[0]), "+f"(c[1]), "+f"(c[2]), "+f"(c[3])
        : "r"(a0), "r"(a1), "r"(a2), "r"(a3), "r"(b0), "r"(b1));
}
// fp16-accumulate variant (double-rate HMMA)
__device__ __forceinline__ void mma16816h(uint32_t& d0, uint32_t& d1,
                                          uint32_t a0, uint32_t a1, uint32_t a2,
                                          uint32_t a3, uint32_t b0, uint32_t b1,
                                          uint32_t c0, uint32_t c1) {
    asm volatile(
        "mma.sync.aligned.m16n8k16.row.col.f16.f16.f16.f16 "
        "{%0,%1}, {%2,%3,%4,%5}, {%6,%7}, {%8,%9};"
        : "=r"(d0), "=r"(d1)
        : "r"(a0), "r"(a1), "r"(a2), "r"(a3), "r"(b0), "r"(b1),
          "r"(c0), "r"(c1));
}

// ------------------------- prepass kernels -------------------------
__global__ void __launch_bounds__(256) weight_prep(
    const float* __restrict__ Wq, const float* __restrict__ bq,
    const float* __restrict__ Wk, const float* __restrict__ bk,
    const float* __restrict__ Wv, const float* __restrict__ bv)
{
    const int idx = blockIdx.x * 256 + threadIdx.x;
    const int m = idx >> 9;
    const int kk = idx & 511;
    const float* src = (m < 512) ? Wq : (m < 1024) ? Wk : Wv;
    g_wc[idx] = __float2half(src[(size_t)(m & 511) * 512 + kk]);
    if (idx < 1536)
        g_bcat[idx] = (idx < 512) ? bq[idx] : (idx < 1024) ? bk[idx - 512] : bv[idx - 1024];
}

__global__ void __launch_bounds__(256) transpose_cvt(const float* __restrict__ X)
{
    __shared__ float t[64][65];
    const int l0 = blockIdx.x * 64;
    const int c0 = blockIdx.y * 64;
    const int b  = blockIdx.z;
    const int tid = threadIdx.x;
    {
        const int r  = tid >> 2;
        const int l4 = (tid & 3) * 4;
        const float* src = X + ((size_t)b * C_ + c0 + r) * HW_ + l0;
        #pragma unroll
        for (int j = 0; j < 4; j++) {
            float4 v = *(const float4*)(src + l4 + j * 16);
            t[r][l4 + j * 16 + 0] = v.x;
            t[r][l4 + j * 16 + 1] = v.y;
            t[r][l4 + j * 16 + 2] = v.z;
            t[r][l4 + j * 16 + 3] = v.w;
        }
    }
    __syncthreads();
    {
        const int l    = tid >> 2;
        const int cseg = (tid & 3) * 16;
        __half2 h2[8];
        #pragma unroll
        for (int j = 0; j < 8; j++)
            h2[j] = __floats2half2_rn(t[cseg + 2 * j][l], t[cseg + 2 * j + 1][l]);
        uint4* dst = (uint4*)(g_xt + ((size_t)b * HW_ + l0 + l) * C_ + c0 + cseg);
        dst[0] = ((uint4*)h2)[0];
        dst[1] = ((uint4*)h2)[1];
    }
}

// ------------------------- fp32-accum HMMA GEMM (KV): CTA 128x256 -------------------------
#define GEMM_STAGE 49152
#define GEMM_SMEM_TOTAL (4 * GEMM_STAGE)

__global__ void __launch_bounds__(256) gemm_kv(
    const __half* __restrict__ A,
    const __half* __restrict__ Bmat,
    const float* __restrict__ bias,
    __half* o0, __half* o1)
{
    extern __shared__ char smem[];
    const uint32_t sbase = smem_u32(smem);
    const int tid  = threadIdx.x;
    const int wid  = tid >> 5;
    const int lane = tid & 31;
    const int wm = wid >> 2;
    const int wn = wid & 3;
    const int n0  = blockIdx.x * 256;
    const int Mg0 = blockIdx.y * 128;
    const int b   = blockIdx.z;
    const size_t bB = (size_t)b * HW_;

    const int rowA  = lane & 15;
    const int kbA   = (lane >> 4) * 16;
    const int nrowB = (lane & 7) + (lane >> 4) * 8;
    const int kbB   = ((lane >> 3) & 1) * 16;

    auto load_chunk = [&](int chunk, int stage) {
        const uint32_t Sb = sbase + stage * GEMM_STAGE;
        const int kc = chunk * 64;
        #pragma unroll
        for (int it = 0; it < 4; it++) {
            int idx = it * 256 + tid;
            int row = idx >> 3, cb = idx & 7;
            cp16(Sb + sw128((uint32_t)(row * 128 + cb * 16)),
                 A + (size_t)(Mg0 + row) * 512 + kc + cb * 8);
        }
        #pragma unroll
        for (int it = 0; it < 8; it++) {
            int idx = it * 256 + tid;
            int row = idx >> 3, cb = idx & 7;
            cp16(Sb + 16384 + sw128((uint32_t)(row * 128 + cb * 16)),
                 Bmat + (bB + n0 + row) * 512 + kc + cb * 8);
        }
        cp_commit();
    };

    float acc[4][8][4];
    #pragma unroll
    for (int i = 0; i < 4; i++)
        #pragma unroll
        for (int j = 0; j < 8; j++)
            #pragma unroll
            for (int r = 0; r < 4; r++) acc[i][j][r] = 0.f;

    uint32_t af[2][16], bf[2][16];

    load_chunk(0, 0);
    load_chunk(1, 1);
    load_chunk(2, 2);

    for (int i = 0; i < 8; i++) {
        if (i <= 5)      cp_wait<2>();
        else if (i == 6) cp_wait<1>();
        else             cp_wait<0>();
        __syncthreads();
        if (i + 3 < 8) load_chunk(i + 3, (i + 3) & 3);

        const uint32_t Ab = sbase + (i & 3) * GEMM_STAGE;
        const uint32_t Bb = Ab + 16384;

        auto ldfrag = [&](int ks, int slot) {
            #pragma unroll
            for (int mi = 0; mi < 4; mi++)
                ldsm4(af[slot][mi * 4 + 0], af[slot][mi * 4 + 1],
                      af[slot][mi * 4 + 2], af[slot][mi * 4 + 3],
                      Ab + sw128((uint32_t)((wm * 64 + mi * 16 + rowA) * 128
                                            + ks * 32 + kbA)));
            #pragma unroll
            for (int nj = 0; nj < 4; nj++)
                ldsm4(bf[slot][nj * 4 + 0], bf[slot][nj * 4 + 1],
                      bf[slot][nj * 4 + 2], bf[slot][nj * 4 + 3],
                      Bb + sw128((uint32_t)((wn * 64 + nj * 16 + nrowB) * 128
                                            + ks * 32 + kbB)));
        };

        ldfrag(0, 0);
        #pragma unroll
        for (int ks = 0; ks < 4; ks++) {
            const int cur = ks & 1;
            if (ks < 3) ldfrag(ks + 1, cur ^ 1);
            #pragma unroll
            for (int mi = 0; mi < 4; mi++)
                #pragma unroll
                for (int n8 = 0; n8 < 8; n8++) {
                    const int nj = n8 >> 1, p = (n8 & 1) * 2;
                    mma16816(acc[mi][n8],
                             af[cur][mi * 4 + 0], af[cur][mi * 4 + 1],
                             af[cur][mi * 4 + 2], af[cur][mi * 4 + 3],
                             bf[cur][nj * 4 + p], bf[cur][nj * 4 + p + 1]);
                }
        }
    }
    __syncthreads();

    const int sel = blockIdx.y >> 2;
    const int mloc_cta = (blockIdx.y & 3) * 128;
    const int ncta0 = n0 + wn * 64 + 2 * (lane & 3);
    #pragma unroll
    for (int mi = 0; mi < 4; mi++) {
        #pragma unroll
        for (int pair = 0; pair < 2; pair++) {
            const int msub = wm * 64 + mi * 16 + (lane >> 2) + pair * 8;
            const float bv = bias[Mg0 + msub];
            __half* outp = (sel == 0) ? o0 : o1;
            __half* rowp = outp + ((size_t)b * 512 + mloc_cta + msub) * HW_;
            #pragma unroll
            for (int n8 = 0; n8 < 8; n8++) {
                __half2 v = __floats2half2_rn(acc[mi][n8][pair * 2 + 0] + bv,
                                              acc[mi][n8][pair * 2 + 1] + bv);
                *(__half2*)(rowp + ncta0 + n8 * 8) = v;
            }
        }
    }
}

// ------------------- fp16-accum HMMA GEMM (Q / final): CTA 128x128, warp 64x32 -------------------
// fp16 accumulation over K=32 chunks (2 chained MMAs from zero), promoted to fp32.
#define G16_STAGE 32768
#define G16_SMEM_TOTAL (3 * G16_STAGE)

template <bool QFUSE>
__global__ void __launch_bounds__(256) gemm_f16acc(
    const __half* __restrict__ A, size_t Astride,
    const __half* __restrict__ Bmat,
    const float* __restrict__ bias,
    float* outp, __half* __restrict__ qt)
{
    extern __shared__ char smem[];
    const uint32_t sbase = smem_u32(smem);
    const int tid  = threadIdx.x;
    const int wid  = tid >> 5;
    const int lane = tid & 31;
    const int wm = wid >> 2;          // 0..1 (64-row half)
    const int wn = wid & 3;           // 0..3 (32-col quarter)
    const int n0  = blockIdx.x * 128;
    const int Mg0 = blockIdx.y * 128;
    const int b   = blockIdx.z;
    const size_t bB = (size_t)b * HW_;
    const __half* Ap = A + (size_t)b * Astride;

    const int rowA  = lane & 15;
    const int kbA   = (lane >> 4) * 16;
    const int nrowB = (lane & 7) + (lane >> 4) * 8;
    const int kbB   = ((lane >> 3) & 1) * 16;

    auto load_chunk = [&](int chunk, int stage) {
        const uint32_t Sb = sbase + stage * G16_STAGE;
        const int kc = chunk * 64;
        #pragma unroll
        for (int it = 0; it < 4; it++) {     // A: 128 rows x 128B
            int idx = it * 256 + tid;
            int row = idx >> 3, cb = idx & 7;
            cp16(Sb + sw128((uint32_t)(row * 128 + cb * 16)),
                 Ap + (size_t)(Mg0 + row) * 512 + kc + cb * 8);
        }
        #pragma unroll
        for (int it = 0; it < 4; it++) {     // B: 128 rows x 128B
            int idx = it * 256 + tid;
            int row = idx >> 3, cb = idx & 7;
            cp16(Sb + 16384 + sw128((uint32_t)(row * 128 + cb * 16)),
                 Bmat + (bB + n0 + row) * 512 + kc + cb * 8);
        }
        cp_commit();
    };

    float acc[4][4][4];
    #pragma unroll
    for (int i = 0; i < 4; i++)
        #pragma unroll
        for (int j = 0; j < 4; j++)
            #pragma unroll
            for (int r = 0; r < 4; r++) acc[i][j][r] = 0.f;

    uint32_t af[2][16], bf[2][8];

    load_chunk(0, 0);
    load_chunk(1, 1);

    for (int i = 0; i < 8; i++) {
        if (i + 1 < 8) cp_wait<1>();
        else           cp_wait<0>();
        __syncthreads();
        if (i + 2 < 8) load_chunk(i + 2, (i + 2) % 3);

        const uint32_t Ab = sbase + (i % 3) * G16_STAGE;
        const uint32_t Bb = Ab + 16384;

        auto ldfrag = [&](int ks, int slot) {
            #pragma unroll
            for (int mi = 0; mi < 4; mi++)
                ldsm4(af[slot][mi * 4 + 0], af[slot][mi * 4 + 1],
                      af[slot][mi * 4 + 2], af[slot][mi * 4 + 3],
                      Ab + sw128((uint32_t)((wm * 64 + mi * 16 + rowA) * 128
                                            + ks * 32 + kbA)));
            #pragma unroll
            for (int j = 0; j < 2; j++)
                ldsm4(bf[slot][j * 4 + 0], bf[slot][j * 4 + 1],
                      bf[slot][j * 4 + 2], bf[slot][j * 4 + 3],
                      Bb + sw128((uint32_t)((wn * 32 + j * 16 + nrowB) * 128
                                            + ks * 32 + kbB)));
        };

        #pragma unroll
        for (int h = 0; h < 2; h++) {        // two k32 sub-chunks
            ldfrag(2 * h, 0);
            ldfrag(2 * h + 1, 1);
            #pragma unroll
            for (int mi = 0; mi < 4; mi++)
                #pragma unroll
                for (int n8 = 0; n8 < 4; n8++) {
                    const int nj = n8 >> 1, p = (n8 & 1) * 2;
                    uint32_t d0, d1;
                    mma16816h(d0, d1,
                              af[0][mi * 4 + 0], af[0][mi * 4 + 1],
                              af[0][mi * 4 + 2], af[0][mi * 4 + 3],
                              bf[0][nj * 4 + p], bf[0][nj * 4 + p + 1],
                              0u, 0u);
                    mma16816h(d0, d1,
                              af[1][mi * 4 + 0], af[1][mi * 4 + 1],
                              af[1][mi * 4 + 2], af[1][mi * 4 + 3],
                              bf[1][nj * 4 + p], bf[1][nj * 4 + p + 1],
                              d0, d1);
                    float2 lo = __half22float2(*(__half2*)&d0);
                    float2 hi = __half22float2(*(__half2*)&d1);
                    acc[mi][n8][0] += lo.x;
                    acc[mi][n8][1] += lo.y;
                    acc[mi][n8][2] += hi.x;
                    acc[mi][n8][3] += hi.y;
                }
        }
    }
    __syncthreads();

    if (QFUSE) {
        // stage fp16 [128 ch][132], column softmax over per-head 64 ch -> qt[b][l][512]
        __half* th = (__half*)smem;
        #pragma unroll
        for (int mi = 0; mi < 4; mi++) {
            #pragma unroll
            for (int pair = 0; pair < 2; pair++) {
                const int ch = wm * 64 + mi * 16 + (lane >> 2) + pair * 8;
                const float bv = bias[Mg0 + ch];
                #pragma unroll
                for (int n8 = 0; n8 < 4; n8++) {
                    const int l = wn * 32 + n8 * 8 + 2 * (lane & 3);
                    *(__half2*)(th + ch * 132 + l) =
                        __floats2half2_rn(acc[mi][n8][0 + pair * 2] + bv,
                                          acc[mi][n8][1 + pair * 2] + bv);
                }
            }
        }
        __syncthreads();
        const int hloc = tid >> 7;            // 0..1
        const int col  = tid & 127;
        float r[64];
        float mx = -1e30f;
        #pragma unroll
        for (int k = 0; k < 64; k++) {
            r[k] = __half2float(th[(hloc * 64 + k) * 132 + col]);
            mx = fmaxf(mx, r[k]);
        }
        float s = 0.f;
        #pragma unroll
        for (int k = 0; k < 64; k++) { r[k] = __expf(r[k] - mx); s += r[k]; }
        const float inv = 1.0f / s;
        __half2 h2[32];
        #pragma unroll
        for (int k = 0; k < 32; k++)
            h2[k] = __floats2half2_rn(r[2 * k] * inv, r[2 * k + 1] * inv);
        uint4* dst = (uint4*)(qt + ((size_t)b * HW_ + n0 + col) * 512
                              + (2 * blockIdx.y + hloc) * 64);
        #pragma unroll
        for (int i = 0; i < 8; i++) dst[i] = ((uint4*)h2)[i];
        return;
    }

    const int ncta0 = n0 + wn * 32 + 2 * (lane & 3);
    #pragma unroll
    for (int mi = 0; mi < 4; mi++) {
        #pragma unroll
        for (int pair = 0; pair < 2; pair++) {
            const int msub = wm * 64 + mi * 16 + (lane >> 2) + pair * 8;
            const float bv = bias[Mg0 + msub];
            float* rowp = outp + ((size_t)b * 512 + blockIdx.y * 128 + msub) * HW_;
            #pragma unroll
            for (int n8 = 0; n8 < 4; n8++) {
                float2 v;
                v.x = acc[mi][n8][pair * 2 + 0] + bv;
                v.y = acc[mi][n8][pair * 2 + 1] + bv;
                *(float2*)(rowp + ncta0 + n8 * 8) = v;
            }
        }
    }
}

// ------------------------- k row stats -------------------------
__global__ void __launch_bounds__(256) kstats(const __half* __restrict__ k)
{
    __shared__ float red[8];
    __shared__ float bb;
    const int row = blockIdx.x;
    const __half2* p2 = (const __half2*)(k + (size_t)row * HW_);
    const int tid = threadIdx.x;

    float2 v[8];
    float mx = -1e30f;
    #pragma unroll
    for (int r = 0; r < 8; r++) {
        v[r] = __half22float2(p2[tid + r * 256]);
        mx = fmaxf(mx, fmaxf(v[r].x, v[r].y));
    }
    #pragma unroll
    for (int o = 16; o > 0; o >>= 1) mx = fmaxf(mx, __shfl_xor_sync(~0u, mx, o));
    if ((tid & 31) == 0) red[tid >> 5] = mx;
    __syncthreads();
    if (tid == 0) {
        float m = red[0];
        #pragma unroll
        for (int i = 1; i < 8; i++) m = fmaxf(m, red[i]);
        bb = m;
    }
    __syncthreads();
    mx = bb;

    float s = 0.f;
    #pragma unroll
    for (int r = 0; r < 8; r++)
        s += __expf(v[r].x - mx) + __expf(v[r].y - mx);
    #pragma unroll
    for (int o = 16; o > 0; o >>= 1) s += __shfl_xor_sync(~0u, s, o);
    if ((tid & 31) == 0) red[tid >> 5] = s;
    __syncthreads();
    if (tid == 0) {
        float m = 0.f;
        #pragma unroll
        for (int i = 0; i < 8; i++) m += red[i];
        g_kmx[row] = mx;
        g_kinv[row] = 1.0f / m;
    }
}

// ------------------------- ctx HMMA split-K with fused k-softmax apply -------------------------
#define CTX_SMEM 32768
__global__ void __launch_bounds__(256) ctx_mma_split(
    const __half* __restrict__ K, const __half* __restrict__ V,
    float* __restrict__ Ctxf)
{
    extern __shared__ char smem[];
    const uint32_t sbase = smem_u32(smem);
    const int bh = blockIdx.x;
    const int sp = blockIdx.y;
    const int tid = threadIdx.x;
    const int wid = tid >> 5;
    const int lane = tid & 31;
    const int wm = wid >> 1;
    const int wn = wid & 1;
    const __half* Kp = K + (size_t)bh * HK_ * HW_;
    const __half* Vp = V + (size_t)bh * HK_ * HW_;

    const int rowA  = lane & 15;
    const int kbA   = (lane >> 4) * 16;
    const int nrowB = (lane & 7) + (lane >> 4) * 8;
    const int kbB   = ((lane >> 3) & 1) * 16;

    const int arow = tid >> 2;
    const int aseg = (tid & 3) * 32;
    const float kmx  = g_kmx[bh * 64 + arow];
    const float kinv = g_kinv[bh * 64 + arow];

    const int nchunks = 64 / CTX_SPLIT;
    const int c0 = sp * nchunks;

    auto load_chunk = [&](int chunk, int buf) {
        const uint32_t Ab = sbase + buf * 16384;
        const uint32_t Bb = Ab + 8192;
        const int lc = chunk * 64;
        #pragma unroll
        for (int it = 0; it < 2; it++) {
            int idx = it * 256 + tid;
            int row = idx >> 3, cb = idx & 7;
            cp16(Ab + sw128((uint32_t)(row * 128 + cb * 16)),
                 Kp + (size_t)row * HW_ + lc + cb * 8);
            cp16(Bb + sw128((uint32_t)(row * 128 + cb * 16)),
                 Vp + (size_t)row * HW_ + lc + cb * 8);
        }
        cp_commit();
    };

    auto apply_exp = [&](uint32_t Kb) {
        #pragma unroll
        for (int t = 0; t < 2; t++) {
            uint32_t addr = Kb + sw128((uint32_t)(arow * 128 + aseg + t * 16));
            uint32_t q0, q1, q2, q3;
            asm volatile("ld.shared.v4.u32 {%0,%1,%2,%3}, [%4];"
                         : "=r"(q0), "=r"(q1), "=r"(q2), "=r"(q3) : "r"(addr));
            uint32_t q[4] = {q0, q1, q2, q3};
            #pragma unroll
            for (int j = 0; j < 4; j++) {
                float2 f = __half22float2(*(__half2*)&q[j]);
                f.x = __expf(f.x - kmx) * kinv;
                f.y = __expf(f.y - kmx) * kinv;
                *(__half2*)&q[j] = __floats2half2_rn(f.x, f.y);
            }
            asm volatile("st.shared.v4.u32 [%0], {%1,%2,%3,%4};"
                         :: "r"(addr), "r"(q[0]), "r"(q[1]), "r"(q[2]), "r"(q[3]));
        }
    };

    float acc[4][4];
    #pragma unroll
    for (int i = 0; i < 4; i++)
        #pragma unroll
        for (int r = 0; r < 4; r++) acc[i][r] = 0.f;

    load_chunk(c0, 0);
    for (int i = 0; i < nchunks; i++) {
        if (i + 1 < nchunks) { load_chunk(c0 + i + 1, (i + 1) & 1); cp_wait<1>(); }
        else                  cp_wait<0>();
        __syncthreads();
        const uint32_t Ab = sbase + (i & 1) * 16384;
        const uint32_t Bb = Ab + 8192;
        apply_exp(Ab);
        __syncthreads();
        #pragma unroll
        for (int ks = 0; ks < 4; ks++) {
            uint32_t a0, a1, a2, a3;
            ldsm4(a0, a1, a2, a3,
                  Ab + sw128((uint32_t)((wm * 16 + rowA) * 128 + ks * 32 + kbA)));
            uint32_t bfr[8];
            #pragma unroll
            for (int j = 0; j < 2; j++)
                ldsm4(bfr[j * 4 + 0], bfr[j * 4 + 1], bfr[j * 4 + 2], bfr[j * 4 + 3],
                      Bb + sw128((uint32_t)((wn * 32 + j * 16 + nrowB) * 128 + ks * 32 + kbB)));
            #pragma unroll
            for (int ni = 0; ni < 4; ni++)
                mma16816(acc[ni], a0, a1, a2, a3, bfr[2 * ni], bfr[2 * ni + 1]);
        }
        __syncthreads();
    }

    float* dst = Ctxf + ((size_t)sp * B_ * HEADS_ + bh) * 4096;
    const int r0 = wm * 16 + (lane >> 2);
    #pragma unroll
    for (int ni = 0; ni < 4; ni++) {
        const int col = wn * 32 + ni * 8 + 2 * (lane & 3);
        dst[r0 * 64 + col]           = acc[ni][0];
        dst[r0 * 64 + col + 1]       = acc[ni][1];
        dst[(r0 + 8) * 64 + col]     = acc[ni][2];
        dst[(r0 + 8) * 64 + col + 1] = acc[ni][3];
    }
}

// ------------------------- M_b = Wr_h @ ctx_h -------------------------
__global__ void __launch_bounds__(256) mb_prep(
    const float* __restrict__ Wr, const float* __restrict__ Ctxf,
    __half* __restrict__ Mb)
{
    __shared__ float ctxs[64][65];
    const int bh = blockIdx.x;
    const int b  = bh >> 3;
    const int h  = bh & 7;
    const int tid = threadIdx.x;
    const int o  = blockIdx.y * 256 + tid;

    const size_t spstride = (size_t)B_ * HEADS_ * 4096;
    const float* c0 = Ctxf + (size_t)bh * 4096;
    #pragma unroll
    for (int i = 0; i < 16; i++) {
        int idx = i * 256 + tid;
        float v = 0.f;
        #pragma unroll
        for (int sp = 0; sp < CTX_SPLIT; sp++)
            v += c0[idx + (size_t)sp * spstride];
        ctxs[idx >> 6][idx & 63] = v;
    }
    __syncthreads();

    float w[64];
    const float4* wr4 = (const float4*)(Wr + (size_t)o * 512 + h * 64);
    #pragma unroll
    for (int i = 0; i < 16; i++) {
        float4 v = wr4[i];
        w[4 * i + 0] = v.x; w[4 * i + 1] = v.y;
        w[4 * i + 2] = v.z; w[4 * i + 3] = v.w;
    }

    __half2 hbuf[32];
    #pragma unroll
    for (int kp = 0; kp < 32; kp++) {
        float s0 = 0.f, s1 = 0.f;
        #pragma unroll
        for (int v = 0; v < 64; v++) {
            s0 += w[v] * ctxs[2 * kp][v];
            s1 += w[v] * ctxs[2 * kp + 1][v];
        }
        hbuf[kp] = __floats2half2_rn(s0, s1);
    }
    uint4* dst = (uint4*)(Mb + ((size_t)b * 512 + o) * 512 + h * 64);
    #pragma unroll
    for (int i = 0; i < 8; i++) dst[i] = ((uint4*)hbuf)[i];
}

// ---------------------------------------------------------------------------
extern "C" void kernel_launch(void* const* d_in, const int* in_sizes, int n_in,
                              void* d_out, int out_size)
{
    const float* x  = (const float*)d_in[0];
    const float* Wk = (const float*)d_in[1];
    const float* bk = (const float*)d_in[2];
    const float* Wq = (const float*)d_in[3];
    const float* bq = (const float*)d_in[4];
    const float* Wv = (const float*)d_in[5];
    const float* bv = (const float*)d_in[6];
    const float* Wr = (const float*)d_in[7];
    const float* br = (const float*)d_in[8];
    float* out = (float*)d_out;

    float *bcat, *ctxf;
    __half *xt, *kh, *vh, *qt, *mb, *wc;
    cudaGetSymbolAddress((void**)&bcat, g_bcat);
    cudaGetSymbolAddress((void**)&xt,   g_xt);
    cudaGetSymbolAddress((void**)&kh,   g_kh);
    cudaGetSymbolAddress((void**)&vh,   g_vh);
    cudaGetSymbolAddress((void**)&qt,   g_qt);
    cudaGetSymbolAddress((void**)&ctxf, g_ctxf);
    cudaGetSymbolAddress((void**)&mb,   g_mb);
    cudaGetSymbolAddress((void**)&wc,   g_wc);

    cudaFuncSetAttribute(gemm_kv,
                         cudaFuncAttributeMaxDynamicSharedMemorySize, GEMM_SMEM_TOTAL);
    cudaFuncSetAttribute(gemm_f16acc<true>,
                         cudaFuncAttributeMaxDynamicSharedMemorySize, G16_SMEM_TOTAL);
    cudaFuncSetAttribute(gemm_f16acc<false>,
                         cudaFuncAttributeMaxDynamicSharedMemorySize, G16_SMEM_TOTAL);

    // prep
    weight_prep<<<3072, 256>>>(Wq, bq, Wk, bk, Wv, bv);
    transpose_cvt<<<dim3(HW_ / 64, C_ / 64, B_), 256>>>(x);

    // KV projection (fp32-accum): k -> kh raw logits, v -> vh
    gemm_kv<<<dim3(16, 8, B_), 256, GEMM_SMEM_TOTAL>>>(
        wc + 512 * 512, xt, bcat + 512, kh, vh);

    // Q projection (fp16-accum, k32 promotion) + fused channel softmax -> qt
    gemm_f16acc<true><<<dim3(32, 4, B_), 256, G16_SMEM_TOTAL>>>(
        wc, 0, xt, bcat, nullptr, qt);

    // k spatial-softmax stats
    kstats<<<B_ * C_, 256>>>(kh);

    // ctx split-K with fused exp application
    ctx_mma_split<<<dim3(B_ * HEADS_, CTX_SPLIT), 256, CTX_SMEM>>>(kh, vh, ctxf);

    // fold Wr into ctx
    mb_prep<<<dim3(B_ * HEADS_, 2), 256>>>(Wr, ctxf, mb);

    // final fused (Wr@ctxT)@qt projection (fp16-accum, k32 promotion)
    gemm_f16acc<false><<<dim3(32, 4, B_), 256, G16_SMEM_TOTAL>>>(
        mb, (size_t)C_ * C_, qt, br, out, nullptr);
}

// round 16
// speedup vs baseline: 1.2036x; 1.2036x over previous
#include <cuda_runtime.h>
#include <cuda_fp16.h>
#include <math.h>
#include <stdint.h>

#define B_ 16
#define C_ 512
#define HW_ 4096
#define HEADS_ 8
#define HK_ 64
#define CTX_SPLIT 8

// ------------------------- scratch (device globals) -------------------------
__device__ __half g_xt[(size_t)B_ * HW_ * C_];   // x transposed fp16 [b][l][c]
__device__ __half g_kh[(size_t)B_ * C_ * HW_];   // raw k logits fp16
__device__ __half g_vh[(size_t)B_ * C_ * HW_];
__device__ __half g_qt[(size_t)B_ * HW_ * C_];   // softmaxed q transposed [b][l][512]
__device__ float  g_ctxf[CTX_SPLIT * B_ * HEADS_ * HK_ * HK_];
__device__ __half g_mb[(size_t)B_ * C_ * C_];    // folded Wr@ctxT [b][o][512]
__device__ __half g_wc[1536 * 512];              // q | k | v weights fp16
__device__ float g_bcat[1536];
__device__ float g_ksum[B_ * C_];                // per-row sum of exp(k) (no max shift)

// ------------------------- PTX helpers -------------------------
__device__ __forceinline__ uint32_t smem_u32(const void* p) {
    return (uint32_t)__cvta_generic_to_shared(p);
}
__device__ __forceinline__ void cp16(uint32_t dst, const void* src) {
    asm volatile("cp.async.cg.shared.global [%0], [%1], 16;\n" :: "r"(dst), "l"(src));
}
__device__ __forceinline__ void cp_commit() {
    asm volatile("cp.async.commit_group;\n" ::: "memory");
}
template <int N>
__device__ __forceinline__ void cp_wait() {
    asm volatile("cp.async.wait_group %0;\n" :: "n"(N) : "memory");
}
__device__ __forceinline__ uint32_t sw128(uint32_t off) {
    return off ^ ((off >> 3) & 0x70);
}
__device__ __forceinline__ void ldsm4(uint32_t& r0, uint32_t& r1, uint32_t& r2,
                                      uint32_t& r3, uint32_t addr) {
    asm volatile("ldmatrix.sync.aligned.m8n8.x4.shared.b16 {%0,%1,%2,%3}, [%4];"
                 : "=r"(r0), "=r"(r1), "=r"(r2), "=r"(r3) : "r"(addr));
}
__device__ __forceinline__ void mma16816(float* c, uint32_t a0, uint32_t a1,
                                         uint32_t a2, uint32_t a3,
                                         uint32_t b0, uint32_t b1) {
    asm volatile(
        "mma.sync.aligned.m16n8k16.row.col.f32.f16.f16.f32 "
        "{%0,%1,%2,%3}, {%4,%5,%6,%7}, {%8,%9}, {%0,%1,%2,%3};"
        : "+f"(c[0]), "+f"(c[1]), "+f"(c[2]), "+f"(c[3])
        : "r"(a0), "r"(a1), "r"(a2), "r"(a3), "r"(b0), "r"(b1));
}

// ------------------------- prepass kernels -------------------------
__global__ void __launch_bounds__(256) weight_prep(
    const float* __restrict__ Wq, const float* __restrict__ bq,
    const float* __restrict__ Wk, const float* __restrict__ bk,
    const float* __restrict__ Wv, const float* __restrict__ bv)
{
    const int idx = blockIdx.x * 256 + threadIdx.x;
    const int m = idx >> 9;
    const int kk = idx & 511;
    const float* src = (m < 512) ? Wq : (m < 1024) ? Wk : Wv;
    g_wc[idx] = __float2half(src[(size_t)(m & 511) * 512 + kk]);
    if (idx < 1536)
        g_bcat[idx] = (idx < 512) ? bq[idx] : (idx < 1024) ? bk[idx - 512] : bv[idx - 1024];
    if (idx < B_ * C_)
        g_ksum[idx] = 0.f;
}

__global__ void __launch_bounds__(256) transpose_cvt(const float* __restrict__ X)
{
    __shared__ float t[64][65];
    const int l0 = blockIdx.x * 64;
    const int c0 = blockIdx.y * 64;
    const int b  = blockIdx.z;
    const int tid = threadIdx.x;
    {
        const int r  = tid >> 2;
        const int l4 = (tid & 3) * 4;
        const float* src = X + ((size_t)b * C_ + c0 + r) * HW_ + l0;
        #pragma unroll
        for (int j = 0; j < 4; j++) {
            float4 v = *(const float4*)(src + l4 + j * 16);
            t[r][l4 + j * 16 + 0] = v.x;
            t[r][l4 + j * 16 + 1] = v.y;
            t[r][l4 + j * 16 + 2] = v.z;
            t[r][l4 + j * 16 + 3] = v.w;
        }
    }
    __syncthreads();
    {
        const int l    = tid >> 2;
        const int cseg = (tid & 3) * 16;
        __half2 h2[8];
        #pragma unroll
        for (int j = 0; j < 8; j++)
            h2[j] = __floats2half2_rn(t[cseg + 2 * j][l], t[cseg + 2 * j + 1][l]);
        uint4* dst = (uint4*)(g_xt + ((size_t)b * HW_ + l0 + l) * C_ + c0 + cseg);
        dst[0] = ((uint4*)h2)[0];
        dst[1] = ((uint4*)h2)[1];
    }
}

// ------------------------- HMMA fp16 GEMM: CTA 128x256, warp 64x64 -------------------------
// 4-stage cp.async pipeline. KSUM: k-half epilogue accumulates per-row sum(exp).
#define GEMM_STAGE 49152
#define GEMM_SMEM_TOTAL (4 * GEMM_STAGE)

template <bool OUT_HALF, bool QFUSE, bool KSUM>
__global__ void __launch_bounds__(256) gemm_mma(
    const __half* __restrict__ A, size_t Astride,
    const __half* __restrict__ Bmat,
    const float* __restrict__ bias,
    void* o0v, void* o1v, __half* __restrict__ qt,
    float* __restrict__ ksum)
{
    extern __shared__ char smem[];
    const uint32_t sbase = smem_u32(smem);
    const int tid  = threadIdx.x;
    const int wid  = tid >> 5;
    const int lane = tid & 31;
    const int wm = wid >> 2;
    const int wn = wid & 3;
    const int n0  = blockIdx.x * 256;
    const int Mg0 = blockIdx.y * 128;
    const int b   = blockIdx.z;
    const size_t bB = (size_t)b * HW_;
    const __half* Ap = A + (size_t)b * Astride;

    const int rowA  = lane & 15;
    const int kbA   = (lane >> 4) * 16;
    const int nrowB = (lane & 7) + (lane >> 4) * 8;
    const int kbB   = ((lane >> 3) & 1) * 16;

    auto load_chunk = [&](int chunk, int stage) {
        const uint32_t Sb = sbase + stage * GEMM_STAGE;
        const int kc = chunk * 64;
        #pragma unroll
        for (int it = 0; it < 4; it++) {
            int idx = it * 256 + tid;
            int row = idx >> 3, cb = idx & 7;
            cp16(Sb + sw128((uint32_t)(row * 128 + cb * 16)),
                 Ap + (size_t)(Mg0 + row) * 512 + kc + cb * 8);
        }
        #pragma unroll
        for (int it = 0; it < 8; it++) {
            int idx = it * 256 + tid;
            int row = idx >> 3, cb = idx & 7;
            cp16(Sb + 16384 + sw128((uint32_t)(row * 128 + cb * 16)),
                 Bmat + (bB + n0 + row) * 512 + kc + cb * 8);
        }
        cp_commit();
    };

    float acc[4][8][4];
    #pragma unroll
    for (int i = 0; i < 4; i++)
        #pragma unroll
        for (int j = 0; j < 8; j++)
            #pragma unroll
            for (int r = 0; r < 4; r++) acc[i][j][r] = 0.f;

    uint32_t af[2][16], bf[2][16];

    load_chunk(0, 0);
    load_chunk(1, 1);
    load_chunk(2, 2);

    for (int i = 0; i < 8; i++) {
        if (i <= 5)      cp_wait<2>();
        else if (i == 6) cp_wait<1>();
        else             cp_wait<0>();
        __syncthreads();
        if (i + 3 < 8) load_chunk(i + 3, (i + 3) & 3);

        const uint32_t Ab = sbase + (i & 3) * GEMM_STAGE;
        const uint32_t Bb = Ab + 16384;

        auto ldfrag = [&](int ks, int slot) {
            #pragma unroll
            for (int mi = 0; mi < 4; mi++)
                ldsm4(af[slot][mi * 4 + 0], af[slot][mi * 4 + 1],
                      af[slot][mi * 4 + 2], af[slot][mi * 4 + 3],
                      Ab + sw128((uint32_t)((wm * 64 + mi * 16 + rowA) * 128
                                            + ks * 32 + kbA)));
            #pragma unroll
            for (int nj = 0; nj < 4; nj++)
                ldsm4(bf[slot][nj * 4 + 0], bf[slot][nj * 4 + 1],
                      bf[slot][nj * 4 + 2], bf[slot][nj * 4 + 3],
                      Bb + sw128((uint32_t)((wn * 64 + nj * 16 + nrowB) * 128
                                            + ks * 32 + kbB)));
        };

        ldfrag(0, 0);
        #pragma unroll
        for (int ks = 0; ks < 4; ks++) {
            const int cur = ks & 1;
            if (ks < 3) ldfrag(ks + 1, cur ^ 1);
            #pragma unroll
            for (int mi = 0; mi < 4; mi++)
                #pragma unroll
                for (int n8 = 0; n8 < 8; n8++) {
                    const int nj = n8 >> 1, p = (n8 & 1) * 2;
                    mma16816(acc[mi][n8],
                             af[cur][mi * 4 + 0], af[cur][mi * 4 + 1],
                             af[cur][mi * 4 + 2], af[cur][mi * 4 + 3],
                             bf[cur][nj * 4 + p], bf[cur][nj * 4 + p + 1]);
                }
        }
    }
    __syncthreads();

    if (QFUSE) {
        // stage fp16 [128 ch][258], column softmax over per-head 64 ch -> qt[b][l][512]
        __half* th = (__half*)smem;
        #pragma unroll
        for (int mi = 0; mi < 4; mi++) {
            #pragma unroll
            for (int pair = 0; pair < 2; pair++) {
                const int ch = wm * 64 + mi * 16 + (lane >> 2) + pair * 8;
                const float bv = bias[Mg0 + ch];
                #pragma unroll
                for (int n8 = 0; n8 < 8; n8++) {
                    const int l = wn * 64 + n8 * 8 + 2 * (lane & 3);
                    *(__half2*)(th + ch * 258 + l) =
                        __floats2half2_rn(acc[mi][n8][pair * 2 + 0] + bv,
                                          acc[mi][n8][pair * 2 + 1] + bv);
                }
            }
        }
        __syncthreads();
        #pragma unroll
        for (int t2 = 0; t2 < 2; t2++) {
            const int task = t2 * 256 + tid;
            const int hloc = task >> 8;
            const int col  = task & 255;
            float r[64];
            float mx = -1e30f;
            #pragma unroll
            for (int k = 0; k < 64; k++) {
                r[k] = __half2float(th[(hloc * 64 + k) * 258 + col]);
                mx = fmaxf(mx, r[k]);
            }
            float s = 0.f;
            #pragma unroll
            for (int k = 0; k < 64; k++) { r[k] = __expf(r[k] - mx); s += r[k]; }
            const float inv = 1.0f / s;
            __half2 h2[32];
            #pragma unroll
            for (int k = 0; k < 32; k++)
                h2[k] = __floats2half2_rn(r[2 * k] * inv, r[2 * k + 1] * inv);
            uint4* dst = (uint4*)(qt + ((size_t)b * HW_ + n0 + col) * 512
                                  + (2 * blockIdx.y + hloc) * 64);
            #pragma unroll
            for (int i = 0; i < 8; i++) dst[i] = ((uint4*)h2)[i];
        }
        return;
    }

    const int sel = blockIdx.y >> 2;
    const int mloc_cta = (blockIdx.y & 3) * 128;
    const int ncta0 = n0 + wn * 64 + 2 * (lane & 3);
    #pragma unroll
    for (int mi = 0; mi < 4; mi++) {
        #pragma unroll
        for (int pair = 0; pair < 2; pair++) {
            const int msub = wm * 64 + mi * 16 + (lane >> 2) + pair * 8;
            const float bv = bias[Mg0 + msub];
            if (OUT_HALF) {
                __half* outp = (__half*)(sel == 0 ? o0v : o1v);
                __half* rowp = outp + ((size_t)b * 512 + mloc_cta + msub) * HW_;
                float esum = 0.f;
                #pragma unroll
                for (int n8 = 0; n8 < 8; n8++) {
                    const float vx = acc[mi][n8][pair * 2 + 0] + bv;
                    const float vy = acc[mi][n8][pair * 2 + 1] + bv;
                    if (KSUM && sel == 0)
                        esum += __expf(vx) + __expf(vy);
                    *(__half2*)(rowp + ncta0 + n8 * 8) = __floats2half2_rn(vx, vy);
                }
                if (KSUM && sel == 0) {
                    // quad reduce (lanes differing in lane&3 share the row)
                    esum += __shfl_xor_sync(~0u, esum, 1);
                    esum += __shfl_xor_sync(~0u, esum, 2);
                    if ((lane & 3) == 0)
                        atomicAdd(ksum + b * 512 + mloc_cta + msub, esum);
                }
            } else {
                float* outp = (float*)(sel == 0 ? o0v : o1v);
                float* rowp = outp + ((size_t)b * 512 + mloc_cta + msub) * HW_;
                #pragma unroll
                for (int n8 = 0; n8 < 8; n8++) {
                    float2 v;
                    v.x = acc[mi][n8][pair * 2 + 0] + bv;
                    v.y = acc[mi][n8][pair * 2 + 1] + bv;
                    *(float2*)(rowp + ncta0 + n8 * 8) = v;
                }
            }
        }
    }
}

// ------------------------- ctx HMMA split-K with fused k-softmax apply -------------------------
#define CTX_SMEM 32768
__global__ void __launch_bounds__(256) ctx_mma_split(
    const __half* __restrict__ K, const __half* __restrict__ V,
    float* __restrict__ Ctxf)
{
    extern __shared__ char smem[];
    const uint32_t sbase = smem_u32(smem);
    const int bh = blockIdx.x;
    const int sp = blockIdx.y;
    const int tid = threadIdx.x;
    const int wid = tid >> 5;
    const int lane = tid & 31;
    const int wm = wid >> 1;
    const int wn = wid & 1;
    const __half* Kp = K + (size_t)bh * HK_ * HW_;
    const __half* Vp = V + (size_t)bh * HK_ * HW_;

    const int rowA  = lane & 15;
    const int kbA   = (lane >> 4) * 16;
    const int nrowB = (lane & 7) + (lane >> 4) * 8;
    const int kbB   = ((lane >> 3) & 1) * 16;

    const int arow = tid >> 2;
    const int aseg = (tid & 3) * 32;
    const float kinv = 1.0f / g_ksum[bh * 64 + arow];

    const int nchunks = 64 / CTX_SPLIT;          // 8
    const int c0 = sp * nchunks;

    auto load_chunk = [&](int chunk, int buf) {
        const uint32_t Ab = sbase + buf * 16384;
        const uint32_t Bb = Ab + 8192;
        const int lc = chunk * 64;
        #pragma unroll
        for (int it = 0; it < 2; it++) {
            int idx = it * 256 + tid;
            int row = idx >> 3, cb = idx & 7;
            cp16(Ab + sw128((uint32_t)(row * 128 + cb * 16)),
                 Kp + (size_t)row * HW_ + lc + cb * 8);
            cp16(Bb + sw128((uint32_t)(row * 128 + cb * 16)),
                 Vp + (size_t)row * HW_ + lc + cb * 8);
        }
        cp_commit();
    };

    auto apply_exp = [&](uint32_t Kb) {
        #pragma unroll
        for (int t = 0; t < 2; t++) {
            uint32_t addr = Kb + sw128((uint32_t)(arow * 128 + aseg + t * 16));
            uint32_t q0, q1, q2, q3;
            asm volatile("ld.shared.v4.u32 {%0,%1,%2,%3}, [%4];"
                         : "=r"(q0), "=r"(q1), "=r"(q2), "=r"(q3) : "r"(addr));
            uint32_t q[4] = {q0, q1, q2, q3};
            #pragma unroll
            for (int j = 0; j < 4; j++) {
                float2 f = __half22float2(*(__half2*)&q[j]);
                f.x = __expf(f.x) * kinv;
                f.y = __expf(f.y) * kinv;
                *(__half2*)&q[j] = __floats2half2_rn(f.x, f.y);
            }
            asm volatile("st.shared.v4.u32 [%0], {%1,%2,%3,%4};"
                         :: "r"(addr), "r"(q[0]), "r"(q[1]), "r"(q[2]), "r"(q[3]));
        }
    };

    float acc[4][4];
    #pragma unroll
    for (int i = 0; i < 4; i++)
        #pragma unroll
        for (int r = 0; r < 4; r++) acc[i][r] = 0.f;

    load_chunk(c0, 0);
    for (int i = 0; i < nchunks; i++) {
        if (i + 1 < nchunks) { load_chunk(c0 + i + 1, (i + 1) & 1); cp_wait<1>(); }
        else                  cp_wait<0>();
        __syncthreads();
        const uint32_t Ab = sbase + (i & 1) * 16384;
        const uint32_t Bb = Ab + 8192;
        apply_exp(Ab);
        __syncthreads();
        #pragma unroll
        for (int ks = 0; ks < 4; ks++) {
            uint32_t a0, a1, a2, a3;
            ldsm4(a0, a1, a2, a3,
                  Ab + sw128((uint32_t)((wm * 16 + rowA) * 128 + ks * 32 + kbA)));
            uint32_t bfr[8];
            #pragma unroll
            for (int j = 0; j < 2; j++)
                ldsm4(bfr[j * 4 + 0], bfr[j * 4 + 1], bfr[j * 4 + 2], bfr[j * 4 + 3],
                      Bb + sw128((uint32_t)((wn * 32 + j * 16 + nrowB) * 128 + ks * 32 + kbB)));
            #pragma unroll
            for (int ni = 0; ni < 4; ni++)
                mma16816(acc[ni], a0, a1, a2, a3, bfr[2 * ni], bfr[2 * ni + 1]);
        }
        __syncthreads();
    }

    float* dst = Ctxf + ((size_t)sp * B_ * HEADS_ + bh) * 4096;
    const int r0 = wm * 16 + (lane >> 2);
    #pragma unroll
    for (int ni = 0; ni < 4; ni++) {
        const int col = wn * 32 + ni * 8 + 2 * (lane & 3);
        dst[r0 * 64 + col]           = acc[ni][0];
        dst[r0 * 64 + col + 1]       = acc[ni][1];
        dst[(r0 + 8) * 64 + col]     = acc[ni][2];
        dst[(r0 + 8) * 64 + col + 1] = acc[ni][3];
    }
}

// ------------------------- M_b = Wr_h @ ctx_h (sums split partials) -------------------------
__global__ void __launch_bounds__(256) mb_prep(
    const float* __restrict__ Wr, const float* __restrict__ Ctxf,
    __half* __restrict__ Mb)
{
    __shared__ float ctxs[64][65];
    const int bh = blockIdx.x;
    const int b  = bh >> 3;
    const int h  = bh & 7;
    const int tid = threadIdx.x;
    const int o  = blockIdx.y * 256 + tid;

    const size_t spstride = (size_t)B_ * HEADS_ * 4096;
    const float* c0 = Ctxf + (size_t)bh * 4096;
    #pragma unroll
    for (int i = 0; i < 16; i++) {
        int idx = i * 256 + tid;
        float v = 0.f;
        #pragma unroll
        for (int sp = 0; sp < CTX_SPLIT; sp++)
            v += c0[idx + (size_t)sp * spstride];
        ctxs[idx >> 6][idx & 63] = v;
    }
    __syncthreads();

    float w[64];
    const float4* wr4 = (const float4*)(Wr + (size_t)o * 512 + h * 64);
    #pragma unroll
    for (int i = 0; i < 16; i++) {
        float4 v = wr4[i];
        w[4 * i + 0] = v.x; w[4 * i + 1] = v.y;
        w[4 * i + 2] = v.z; w[4 * i + 3] = v.w;
    }

    __half2 hbuf[32];
    #pragma unroll
    for (int kp = 0; kp < 32; kp++) {
        float s0 = 0.f, s1 = 0.f;
        #pragma unroll
        for (int v = 0; v < 64; v++) {
            s0 += w[v] * ctxs[2 * kp][v];
            s1 += w[v] * ctxs[2 * kp + 1][v];
        }
        hbuf[kp] = __floats2half2_rn(s0, s1);
    }
    uint4* dst = (uint4*)(Mb + ((size_t)b * 512 + o) * 512 + h * 64);
    #pragma unroll
    for (int i = 0; i < 8; i++) dst[i] = ((uint4*)hbuf)[i];
}

// ---------------------------------------------------------------------------
extern "C" void kernel_launch(void* const* d_in, const int* in_sizes, int n_in,
                              void* d_out, int out_size)
{
    const float* x  = (const float*)d_in[0];
    const float* Wk = (const float*)d_in[1];
    const float* bk = (const float*)d_in[2];
    const float* Wq = (const float*)d_in[3];
    const float* bq = (const float*)d_in[4];
    const float* Wv = (const float*)d_in[5];
    const float* bv = (const float*)d_in[6];
    const float* Wr = (const float*)d_in[7];
    const float* br = (const float*)d_in[8];
    float* out = (float*)d_out;

    float *bcat, *ctxf, *ksum;
    __half *xt, *kh, *vh, *qt, *mb, *wc;
    cudaGetSymbolAddress((void**)&bcat, g_bcat);
    cudaGetSymbolAddress((void**)&xt,   g_xt);
    cudaGetSymbolAddress((void**)&kh,   g_kh);
    cudaGetSymbolAddress((void**)&vh,   g_vh);
    cudaGetSymbolAddress((void**)&qt,   g_qt);
    cudaGetSymbolAddress((void**)&ctxf, g_ctxf);
    cudaGetSymbolAddress((void**)&mb,   g_mb);
    cudaGetSymbolAddress((void**)&wc,   g_wc);
    cudaGetSymbolAddress((void**)&ksum, g_ksum);

    cudaFuncSetAttribute((const void*)gemm_mma<true, false, true>,
                         cudaFuncAttributeMaxDynamicSharedMemorySize, GEMM_SMEM_TOTAL);
    cudaFuncSetAttribute((const void*)gemm_mma<true, true, false>,
                         cudaFuncAttributeMaxDynamicSharedMemorySize, GEMM_SMEM_TOTAL);
    cudaFuncSetAttribute((const void*)gemm_mma<false, false, false>,
                         cudaFuncAttributeMaxDynamicSharedMemorySize, GEMM_SMEM_TOTAL);

    // prep (also zeros ksum)
    weight_prep<<<3072, 256>>>(Wq, bq, Wk, bk, Wv, bv);
    transpose_cvt<<<dim3(HW_ / 64, C_ / 64, B_), 256>>>(x);

    // KV projection: k -> kh (+ per-row exp-sum), v -> vh
    gemm_mma<true, false, true><<<dim3(16, 8, B_), 256, GEMM_SMEM_TOTAL>>>(
        wc + 512 * 512, 0, xt, bcat + 512, kh, vh, nullptr, ksum);

    // Q projection with fused channel softmax -> qt[b][l][512]
    gemm_mma<true, true, false><<<dim3(16, 4, B_), 256, GEMM_SMEM_TOTAL>>>(
        wc, 0, xt, bcat, nullptr, nullptr, qt, nullptr);

    // ctx split-K with fused exp/normalize
    ctx_mma_split<<<dim3(B_ * HEADS_, CTX_SPLIT), 256, CTX_SMEM>>>(kh, vh, ctxf);

    // fold Wr into ctx
    mb_prep<<<dim3(B_ * HEADS_, 2), 256>>>(Wr, ctxf, mb);

    // final fused (Wr@ctxT)@qt projection
    gemm_mma<false, false, false><<<dim3(16, 4, B_), 256, GEMM_SMEM_TOTAL>>>(
        mb, (size_t)C_ * C_, qt, br, out, out, nullptr, nullptr);
}

// round 17
// speedup vs baseline: 1.2266x; 1.0191x over previous
#include <cuda_runtime.h>
#include <cuda_fp16.h>
#include <math.h>
#include <stdint.h>

#define B_ 16
#define C_ 512
#define HW_ 4096
#define HEADS_ 8
#define HK_ 64
#define CTX_SPLIT 8

// ------------------------- scratch (device globals) -------------------------
__device__ __half g_xt[(size_t)B_ * HW_ * C_];   // x transposed fp16 [b][l][c]
__device__ __half g_kh[(size_t)B_ * C_ * HW_];   // raw k logits fp16
__device__ __half g_vh[(size_t)B_ * C_ * HW_];
__device__ __half g_qt[(size_t)B_ * HW_ * C_];   // softmaxed q transposed [b][l][512]
__device__ float  g_ctxf[CTX_SPLIT * B_ * HEADS_ * HK_ * HK_];
__device__ __half g_mb[(size_t)B_ * C_ * C_];    // folded Wr@ctxT [b][o][512]
__device__ __half g_wc[1536 * 512];              // q | k | v weights fp16
__device__ float g_bcat[1536];
__device__ float g_ksum[B_ * C_];                // per-row sum of exp(k)

// ------------------------- PTX helpers -------------------------
__device__ __forceinline__ uint32_t smem_u32(const void* p) {
    return (uint32_t)__cvta_generic_to_shared(p);
}
__device__ __forceinline__ void cp16(uint32_t dst, const void* src) {
    asm volatile("cp.async.cg.shared.global [%0], [%1], 16;\n" :: "r"(dst), "l"(src));
}
__device__ __forceinline__ void cp_commit() {
    asm volatile("cp.async.commit_group;\n" ::: "memory");
}
template <int N>
__device__ __forceinline__ void cp_wait() {
    asm volatile("cp.async.wait_group %0;\n" :: "n"(N) : "memory");
}
__device__ __forceinline__ uint32_t sw128(uint32_t off) {
    return off ^ ((off >> 3) & 0x70);
}
__device__ __forceinline__ void ldsm4(uint32_t& r0, uint32_t& r1, uint32_t& r2,
                                      uint32_t& r3, uint32_t addr) {
    asm volatile("ldmatrix.sync.aligned.m8n8.x4.shared.b16 {%0,%1,%2,%3}, [%4];"
                 : "=r"(r0), "=r"(r1), "=r"(r2), "=r"(r3) : "r"(addr));
}
__device__ __forceinline__ void mma16816(float* c, uint32_t a0, uint32_t a1,
                                         uint32_t a2, uint32_t a3,
                                         uint32_t b0, uint32_t b1) {
    asm volatile(
        "mma.sync.aligned.m16n8k16.row.col.f32.f16.f16.f32 "
        "{%0,%1,%2,%3}, {%4,%5,%6,%7}, {%8,%9}, {%0,%1,%2,%3};"
        : "+f"(c[0]), "+f"(c[1]), "+f"(c[2]), "+f"(c[3])
        : "r"(a0), "r"(a1), "r"(a2), "r"(a3), "r"(b0), "r"(b1));
}

// ------------------------- merged prepass: transpose x + weight convert -------------------------
__global__ void __launch_bounds__(256) prep_all(
    const float* __restrict__ X,
    const float* __restrict__ Wq, const float* __restrict__ bq,
    const float* __restrict__ Wk, const float* __restrict__ bk,
    const float* __restrict__ Wv, const float* __restrict__ bv)
{
    __shared__ float t[64][65];
    const int tid = threadIdx.x;

    if (blockIdx.x < 8192) {
        // transpose/convert: bx -> (l-tile, c-tile, batch)
        const int bx = blockIdx.x;
        const int l0 = (bx & 63) * 64;
        const int c0 = ((bx >> 6) & 7) * 64;
        const int b  = bx >> 9;
        {
            const int r  = tid >> 2;
            const int l4 = (tid & 3) * 4;
            const float* src = X + ((size_t)b * C_ + c0 + r) * HW_ + l0;
            #pragma unroll
            for (int j = 0; j < 4; j++) {
                float4 v = *(const float4*)(src + l4 + j * 16);
                t[r][l4 + j * 16 + 0] = v.x;
                t[r][l4 + j * 16 + 1] = v.y;
                t[r][l4 + j * 16 + 2] = v.z;
                t[r][l4 + j * 16 + 3] = v.w;
            }
        }
        __syncthreads();
        {
            const int l    = tid >> 2;
            const int cseg = (tid & 3) * 16;
            __half2 h2[8];
            #pragma unroll
            for (int j = 0; j < 8; j++)
                h2[j] = __floats2half2_rn(t[cseg + 2 * j][l], t[cseg + 2 * j + 1][l]);
            uint4* dst = (uint4*)(g_xt + ((size_t)b * HW_ + l0 + l) * C_ + c0 + cseg);
            dst[0] = ((uint4*)h2)[0];
            dst[1] = ((uint4*)h2)[1];
        }
    } else {
        const int idx = (blockIdx.x - 8192) * 256 + tid;   // < 1536*512
        const int m = idx >> 9;
        const int kk = idx & 511;
        const float* src = (m < 512) ? Wq : (m < 1024) ? Wk : Wv;
        g_wc[idx] = __float2half(src[(size_t)(m & 511) * 512 + kk]);
        if (idx < 1536)
            g_bcat[idx] = (idx < 512) ? bq[idx]
                        : (idx < 1024) ? bk[idx - 512] : bv[idx - 1024];
        if (idx < B_ * C_)
            g_ksum[idx] = 0.f;
    }
}

// ------------------------- HMMA fp16 GEMM: CTA 128x256, warp 64x64 -------------------------
// 4-stage cp.async pipeline.
// QKV mode: sel==0 -> fused q channel-softmax into qt; sel==1 -> k (+exp-sum); sel==2 -> v.
#define GEMM_STAGE 49152
#define GEMM_SMEM_TOTAL (4 * GEMM_STAGE)

template <bool QKV>
__global__ void __launch_bounds__(256) gemm_mma(
    const __half* __restrict__ A, size_t Astride,
    const __half* __restrict__ Bmat,
    const float* __restrict__ bias,
    void* o0v, void* o1v, __half* __restrict__ qt,
    float* __restrict__ ksum)
{
    extern __shared__ char smem[];
    const uint32_t sbase = smem_u32(smem);
    const int tid  = threadIdx.x;
    const int wid  = tid >> 5;
    const int lane = tid & 31;
    const int wm = wid >> 2;
    const int wn = wid & 3;
    const int n0  = blockIdx.x * 256;
    const int Mg0 = blockIdx.y * 128;
    const int b   = blockIdx.z;
    const size_t bB = (size_t)b * HW_;
    const __half* Ap = A + (size_t)b * Astride;

    const int rowA  = lane & 15;
    const int kbA   = (lane >> 4) * 16;
    const int nrowB = (lane & 7) + (lane >> 4) * 8;
    const int kbB   = ((lane >> 3) & 1) * 16;

    auto load_chunk = [&](int chunk, int stage) {
        const uint32_t Sb = sbase + stage * GEMM_STAGE;
        const int kc = chunk * 64;
        #pragma unroll
        for (int it = 0; it < 4; it++) {
            int idx = it * 256 + tid;
            int row = idx >> 3, cb = idx & 7;
            cp16(Sb + sw128((uint32_t)(row * 128 + cb * 16)),
                 Ap + (size_t)(Mg0 + row) * 512 + kc + cb * 8);
        }
        #pragma unroll
        for (int it = 0; it < 8; it++) {
            int idx = it * 256 + tid;
            int row = idx >> 3, cb = idx & 7;
            cp16(Sb + 16384 + sw128((uint32_t)(row * 128 + cb * 16)),
                 Bmat + (bB + n0 + row) * 512 + kc + cb * 8);
        }
        cp_commit();
    };

    float acc[4][8][4];
    #pragma unroll
    for (int i = 0; i < 4; i++)
        #pragma unroll
        for (int j = 0; j < 8; j++)
            #pragma unroll
            for (int r = 0; r < 4; r++) acc[i][j][r] = 0.f;

    uint32_t af[2][16], bf[2][16];

    load_chunk(0, 0);
    load_chunk(1, 1);
    load_chunk(2, 2);

    for (int i = 0; i < 8; i++) {
        if (i <= 5)      cp_wait<2>();
        else if (i == 6) cp_wait<1>();
        else             cp_wait<0>();
        __syncthreads();
        if (i + 3 < 8) load_chunk(i + 3, (i + 3) & 3);

        const uint32_t Ab = sbase + (i & 3) * GEMM_STAGE;
        const uint32_t Bb = Ab + 16384;

        auto ldfrag = [&](int ks, int slot) {
            #pragma unroll
            for (int mi = 0; mi < 4; mi++)
                ldsm4(af[slot][mi * 4 + 0], af[slot][mi * 4 + 1],
                      af[slot][mi * 4 + 2], af[slot][mi * 4 + 3],
                      Ab + sw128((uint32_t)((wm * 64 + mi * 16 + rowA) * 128
                                            + ks * 32 + kbA)));
            #pragma unroll
            for (int nj = 0; nj < 4; nj++)
                ldsm4(bf[slot][nj * 4 + 0], bf[slot][nj * 4 + 1],
                      bf[slot][nj * 4 + 2], bf[slot][nj * 4 + 3],
                      Bb + sw128((uint32_t)((wn * 64 + nj * 16 + nrowB) * 128
                                            + ks * 32 + kbB)));
        };

        ldfrag(0, 0);
        #pragma unroll
        for (int ks = 0; ks < 4; ks++) {
            const int cur = ks & 1;
            if (ks < 3) ldfrag(ks + 1, cur ^ 1);
            #pragma unroll
            for (int mi = 0; mi < 4; mi++)
                #pragma unroll
                for (int n8 = 0; n8 < 8; n8++) {
                    const int nj = n8 >> 1, p = (n8 & 1) * 2;
                    mma16816(acc[mi][n8],
                             af[cur][mi * 4 + 0], af[cur][mi * 4 + 1],
                             af[cur][mi * 4 + 2], af[cur][mi * 4 + 3],
                             bf[cur][nj * 4 + p], bf[cur][nj * 4 + p + 1]);
                }
        }
    }
    __syncthreads();

    const int sel = blockIdx.y >> 2;

    if (QKV && sel == 0) {
        // fused q channel softmax + transpose -> qt[b][l][512]
        __half* th = (__half*)smem;
        #pragma unroll
        for (int mi = 0; mi < 4; mi++) {
            #pragma unroll
            for (int pair = 0; pair < 2; pair++) {
                const int ch = wm * 64 + mi * 16 + (lane >> 2) + pair * 8;
                const float bv = bias[Mg0 + ch];
                #pragma unroll
                for (int n8 = 0; n8 < 8; n8++) {
                    const int l = wn * 64 + n8 * 8 + 2 * (lane & 3);
                    *(__half2*)(th + ch * 258 + l) =
                        __floats2half2_rn(acc[mi][n8][pair * 2 + 0] + bv,
                                          acc[mi][n8][pair * 2 + 1] + bv);
                }
            }
        }
        __syncthreads();
        #pragma unroll
        for (int t2 = 0; t2 < 2; t2++) {
            const int task = t2 * 256 + tid;
            const int hloc = task >> 8;
            const int col  = task & 255;
            float r[64];
            float mx = -1e30f;
            #pragma unroll
            for (int k = 0; k < 64; k++) {
                r[k] = __half2float(th[(hloc * 64 + k) * 258 + col]);
                mx = fmaxf(mx, r[k]);
            }
            float s = 0.f;
            #pragma unroll
            for (int k = 0; k < 64; k++) { r[k] = __expf(r[k] - mx); s += r[k]; }
            const float inv = 1.0f / s;
            __half2 h2[32];
            #pragma unroll
            for (int k = 0; k < 32; k++)
                h2[k] = __floats2half2_rn(r[2 * k] * inv, r[2 * k + 1] * inv);
            uint4* dst = (uint4*)(qt + ((size_t)b * HW_ + n0 + col) * 512
                                  + (2 * blockIdx.y + hloc) * 64);
            #pragma unroll
            for (int i = 0; i < 8; i++) dst[i] = ((uint4*)h2)[i];
        }
        return;
    }

    const int mloc_cta = (blockIdx.y & 3) * 128;
    const int ncta0 = n0 + wn * 64 + 2 * (lane & 3);
    #pragma unroll
    for (int mi = 0; mi < 4; mi++) {
        #pragma unroll
        for (int pair = 0; pair < 2; pair++) {
            const int msub = wm * 64 + mi * 16 + (lane >> 2) + pair * 8;
            const float bv = bias[Mg0 + msub];
            if (QKV) {
                // sel==1 -> k (o0v, + exp-sum); sel==2 -> v (o1v)
                __half* outp = (__half*)(sel == 1 ? o0v : o1v);
                __half* rowp = outp + ((size_t)b * 512 + mloc_cta + msub) * HW_;
                float esum = 0.f;
                #pragma unroll
                for (int n8 = 0; n8 < 8; n8++) {
                    const float vx = acc[mi][n8][pair * 2 + 0] + bv;
                    const float vy = acc[mi][n8][pair * 2 + 1] + bv;
                    if (sel == 1) esum += __expf(vx) + __expf(vy);
                    *(__half2*)(rowp + ncta0 + n8 * 8) = __floats2half2_rn(vx, vy);
                }
                if (sel == 1) {
                    esum += __shfl_xor_sync(~0u, esum, 1);
                    esum += __shfl_xor_sync(~0u, esum, 2);
                    if ((lane & 3) == 0)
                        atomicAdd(ksum + b * 512 + mloc_cta + msub, esum);
                }
            } else {
                float* outp = (float*)o0v;
                float* rowp = outp + ((size_t)b * 512 + mloc_cta + msub) * HW_;
                #pragma unroll
                for (int n8 = 0; n8 < 8; n8++) {
                    float2 v;
                    v.x = acc[mi][n8][pair * 2 + 0] + bv;
                    v.y = acc[mi][n8][pair * 2 + 1] + bv;
                    *(float2*)(rowp + ncta0 + n8 * 8) = v;
                }
            }
        }
    }
}

// ------------------------- ctx HMMA split-K with fused k-softmax apply -------------------------
#define CTX_SMEM 32768
__global__ void __launch_bounds__(256) ctx_mma_split(
    const __half* __restrict__ K, const __half* __restrict__ V,
    float* __restrict__ Ctxf)
{
    extern __shared__ char smem[];
    const uint32_t sbase = smem_u32(smem);
    const int bh = blockIdx.x;
    const int sp = blockIdx.y;
    const int tid = threadIdx.x;
    const int wid = tid >> 5;
    const int lane = tid & 31;
    const int wm = wid >> 1;
    const int wn = wid & 1;
    const __half* Kp = K + (size_t)bh * HK_ * HW_;
    const __half* Vp = V + (size_t)bh * HK_ * HW_;

    const int rowA  = lane & 15;
    const int kbA   = (lane >> 4) * 16;
    const int nrowB = (lane & 7) + (lane >> 4) * 8;
    const int kbB   = ((lane >> 3) & 1) * 16;

    const int arow = tid >> 2;
    const int aseg = (tid & 3) * 32;
    const float kinv = 1.0f / g_ksum[bh * 64 + arow];

    const int nchunks = 64 / CTX_SPLIT;
    const int c0 = sp * nchunks;

    auto load_chunk = [&](int chunk, int buf) {
        const uint32_t Ab = sbase + buf * 16384;
        const uint32_t Bb = Ab + 8192;
        const int lc = chunk * 64;
        #pragma unroll
        for (int it = 0; it < 2; it++) {
            int idx = it * 256 + tid;
            int row = idx >> 3, cb = idx & 7;
            cp16(Ab + sw128((uint32_t)(row * 128 + cb * 16)),
                 Kp + (size_t)row * HW_ + lc + cb * 8);
            cp16(Bb + sw128((uint32_t)(row * 128 + cb * 16)),
                 Vp + (size_t)row * HW_ + lc + cb * 8);
        }
        cp_commit();
    };

    auto apply_exp = [&](uint32_t Kb) {
        #pragma unroll
        for (int t = 0; t < 2; t++) {
            uint32_t addr = Kb + sw128((uint32_t)(arow * 128 + aseg + t * 16));
            uint32_t q0, q1, q2, q3;
            asm volatile("ld.shared.v4.u32 {%0,%1,%2,%3}, [%4];"
                         : "=r"(q0), "=r"(q1), "=r"(q2), "=r"(q3) : "r"(addr));
            uint32_t q[4] = {q0, q1, q2, q3};
            #pragma unroll
            for (int j = 0; j < 4; j++) {
                float2 f = __half22float2(*(__half2*)&q[j]);
                f.x = __expf(f.x) * kinv;
                f.y = __expf(f.y) * kinv;
                *(__half2*)&q[j] = __floats2half2_rn(f.x, f.y);
            }
            asm volatile("st.shared.v4.u32 [%0], {%1,%2,%3,%4};"
                         :: "r"(addr), "r"(q[0]), "r"(q[1]), "r"(q[2]), "r"(q[3]));
        }
    };

    float acc[4][4];
    #pragma unroll
    for (int i = 0; i < 4; i++)
        #pragma unroll
        for (int r = 0; r < 4; r++) acc[i][r] = 0.f;

    load_chunk(c0, 0);
    for (int i = 0; i < nchunks; i++) {
        if (i + 1 < nchunks) { load_chunk(c0 + i + 1, (i + 1) & 1); cp_wait<1>(); }
        else                  cp_wait<0>();
        __syncthreads();
        const uint32_t Ab = sbase + (i & 1) * 16384;
        const uint32_t Bb = Ab + 8192;
        apply_exp(Ab);
        __syncthreads();
        #pragma unroll
        for (int ks = 0; ks < 4; ks++) {
            uint32_t a0, a1, a2, a3;
            ldsm4(a0, a1, a2, a3,
                  Ab + sw128((uint32_t)((wm * 16 + rowA) * 128 + ks * 32 + kbA)));
            uint32_t bfr[8];
            #pragma unroll
            for (int j = 0; j < 2; j++)
                ldsm4(bfr[j * 4 + 0], bfr[j * 4 + 1], bfr[j * 4 + 2], bfr[j * 4 + 3],
                      Bb + sw128((uint32_t)((wn * 32 + j * 16 + nrowB) * 128 + ks * 32 + kbB)));
            #pragma unroll
            for (int ni = 0; ni < 4; ni++)
                mma16816(acc[ni], a0, a1, a2, a3, bfr[2 * ni], bfr[2 * ni + 1]);
        }
        __syncthreads();
    }

    float* dst = Ctxf + ((size_t)sp * B_ * HEADS_ + bh) * 4096;
    const int r0 = wm * 16 + (lane >> 2);
    #pragma unroll
    for (int ni = 0; ni < 4; ni++) {
        const int col = wn * 32 + ni * 8 + 2 * (lane & 3);
        dst[r0 * 64 + col]           = acc[ni][0];
        dst[r0 * 64 + col + 1]       = acc[ni][1];
        dst[(r0 + 8) * 64 + col]     = acc[ni][2];
        dst[(r0 + 8) * 64 + col + 1] = acc[ni][3];
    }
}

// ------------------------- M_b = Wr_h @ ctx_h (sums split partials) -------------------------
__global__ void __launch_bounds__(256) mb_prep(
    const float* __restrict__ Wr, const float* __restrict__ Ctxf,
    __half* __restrict__ Mb)
{
    __shared__ float ctxs[64][65];
    const int bh = blockIdx.x;
    const int b  = bh >> 3;
    const int h  = bh & 7;
    const int tid = threadIdx.x;
    const int o  = blockIdx.y * 256 + tid;

    const size_t spstride = (size_t)B_ * HEADS_ * 4096;
    const float* c0 = Ctxf + (size_t)bh * 4096;
    #pragma unroll
    for (int i = 0; i < 16; i++) {
        int idx = i * 256 + tid;
        float v = 0.f;
        #pragma unroll
        for (int sp = 0; sp < CTX_SPLIT; sp++)
            v += c0[idx + (size_t)sp * spstride];
        ctxs[idx >> 6][idx & 63] = v;
    }
    __syncthreads();

    float w[64];
    const float4* wr4 = (const float4*)(Wr + (size_t)o * 512 + h * 64);
    #pragma unroll
    for (int i = 0; i < 16; i++) {
        float4 v = wr4[i];
        w[4 * i + 0] = v.x; w[4 * i + 1] = v.y;
        w[4 * i + 2] = v.z; w[4 * i + 3] = v.w;
    }

    __half2 hbuf[32];
    #pragma unroll
    for (int kp = 0; kp < 32; kp++) {
        float s0 = 0.f, s1 = 0.f;
        #pragma unroll
        for (int v = 0; v < 64; v++) {
            s0 += w[v] * ctxs[2 * kp][v];
            s1 += w[v] * ctxs[2 * kp + 1][v];
        }
        hbuf[kp] = __floats2half2_rn(s0, s1);
    }
    uint4* dst = (uint4*)(Mb + ((size_t)b * 512 + o) * 512 + h * 64);
    #pragma unroll
    for (int i = 0; i < 8; i++) dst[i] = ((uint4*)hbuf)[i];
}

// ---------------------------------------------------------------------------
extern "C" void kernel_launch(void* const* d_in, const int* in_sizes, int n_in,
                              void* d_out, int out_size)
{
    const float* x  = (const float*)d_in[0];
    const float* Wk = (const float*)d_in[1];
    const float* bk = (const float*)d_in[2];
    const float* Wq = (const float*)d_in[3];
    const float* bq = (const float*)d_in[4];
    const float* Wv = (const float*)d_in[5];
    const float* bv = (const float*)d_in[6];
    const float* Wr = (const float*)d_in[7];
    const float* br = (const float*)d_in[8];
    float* out = (float*)d_out;

    float *bcat, *ctxf, *ksum;
    __half *xt, *kh, *vh, *qt, *mb, *wc;
    cudaGetSymbolAddress((void**)&bcat, g_bcat);
    cudaGetSymbolAddress((void**)&xt,   g_xt);
    cudaGetSymbolAddress((void**)&kh,   g_kh);
    cudaGetSymbolAddress((void**)&vh,   g_vh);
    cudaGetSymbolAddress((void**)&qt,   g_qt);
    cudaGetSymbolAddress((void**)&ctxf, g_ctxf);
    cudaGetSymbolAddress((void**)&mb,   g_mb);
    cudaGetSymbolAddress((void**)&wc,   g_wc);
    cudaGetSymbolAddress((void**)&ksum, g_ksum);

    cudaFuncSetAttribute((const void*)gemm_mma<true>,
                         cudaFuncAttributeMaxDynamicSharedMemorySize, GEMM_SMEM_TOTAL);
    cudaFuncSetAttribute((const void*)gemm_mma<false>,
                         cudaFuncAttributeMaxDynamicSharedMemorySize, GEMM_SMEM_TOTAL);

    // merged prepass: transpose/convert x + weight convert + ksum zero
    prep_all<<<8192 + 3072, 256>>>(x, Wq, bq, Wk, bk, Wv, bv);

    // fused QKV projection (single launch):
    //   y 0-3: q -> channel softmax -> qt; y 4-7: k -> kh (+exp-sum); y 8-11: v -> vh
    gemm_mma<true><<<dim3(16, 12, B_), 256, GEMM_SMEM_TOTAL>>>(
        wc, 0, xt, bcat, kh, vh, qt, ksum);

    // ctx split-K with fused exp/normalize
    ctx_mma_split<<<dim3(B_ * HEADS_, CTX_SPLIT), 256, CTX_SMEM>>>(kh, vh, ctxf);

    // fold Wr into ctx
    mb_prep<<<dim3(B_ * HEADS_, 2), 256>>>(Wr, ctxf, mb);

    // final fused (Wr@ctxT)@qt projection
    gemm_mma<false><<<dim3(16, 4, B_), 256, GEMM_SMEM_TOTAL>>>(
        mb, (size_t)C_ * C_, qt, br, out, nullptr, nullptr, nullptr);
}